// round 7
// baseline (speedup 1.0000x reference)
#include <cuda_runtime.h>
#include <float.h>

// ROI adaptive max pool 7x7 — separable, float4, static lane remap.
// images: [8,256,56,56] f32; rois: [256,4] f32; roi_idx: [256] i32
// out: [256,256,7,7] f32
//
// Block = (roi, 32-channel group), blockDim (8,32) = 256 threads.
// Thread (tx, ch) owns quad slots {tx, tx+8}; only slots in [qlo,qhi) run.
// Residues of ~6 active quads hit ~6 of 8 tx lanes -> ~75-100% lane use
// (vs 36% with 16 fixed slots), each active slot running the fully
// unrolled 7-bin float4 pipeline (high MLP, R5 body).
// rowp is 53.9KB -> dynamic smem + cudaFuncSetAttribute (host-side, capture-safe).

#define Hc 56
#define Wc 56
#define Cc 256
#define Rc 256
#define OUTN 7
#define CPB 32
#define W4 (Wc / 4)        // 14
#define CHW4 (Hc * W4)     // 784 float4 per channel
#define ROWP_STRIDE 60     // floats per (ch,bin) row

__global__ __launch_bounds__(256) void roipool_kernel(
    const float* __restrict__ images,
    const float* __restrict__ rois,
    const int* __restrict__ roi_idx,
    float* __restrict__ out)
{
    extern __shared__ float smem[];
    float* rowp = smem;                               // [CPB][OUTN][60]
    int*   sb   = (int*)(smem + CPB * OUTN * ROWP_STRIDE);  // [28]

    const int r   = blockIdx.y;
    const int cg  = blockIdx.x;
    const int tx  = threadIdx.x;           // 0..7 quad slot
    const int ch  = threadIdx.y;           // 0..31 channel
    const int tid = ch * 8 + tx;

    const float4 rv = ((const float4*)rois)[r];
    const int x1 = (int)floorf(rv.x * (float)Wc);
    const int y1 = (int)floorf(rv.y * (float)Hc);
    const int x2 = (int)ceilf (rv.z * (float)Wc);
    const int y2 = (int)ceilf (rv.w * (float)Hc);

    // Bin-bounds table: ys[7] ye[7] xs[7] xe[7]
    if (tid < 28) {
        const int g = tid / OUTN;
        const int i = tid - g * OUTN;
        const int Hr = y2 - y1, Wr = x2 - x1;
        int v;
        if (g == 0)      v = y1 + (i * Hr) / OUTN;
        else if (g == 1) v = y1 + ((i + 1) * Hr + OUTN - 1) / OUTN;
        else if (g == 2) v = x1 + (i * Wr) / OUTN;
        else             v = x1 + ((i + 1) * Wr + OUTN - 1) / OUTN;
        sb[tid] = v;
    }
    __syncthreads();

    const int n = roi_idx[r];
    const float4* __restrict__ imgc =
        (const float4*)images + (size_t)(n * Cc + cg * CPB + ch) * CHW4;
    float* __restrict__ rowc = rowp + ch * (OUTN * ROWP_STRIDE);

    const int qlo = x1 >> 2;
    const int qhi = (x2 + 3) >> 2;

    // ---- Phase 1: row-bin maxes; slots tx and tx+8 ----
    #pragma unroll
    for (int pass = 0; pass < 2; pass++) {
        const int q = tx + pass * 8;
        if (q >= qlo && q < qhi) {
            const float4* __restrict__ base = imgc + q;
            #pragma unroll
            for (int i = 0; i < OUTN; i++) {
                const int s = sb[i], e = sb[7 + i];
                float4 m = make_float4(-FLT_MAX, -FLT_MAX, -FLT_MAX, -FLT_MAX);
                const float4* p = base + s * W4;
                #pragma unroll 2
                for (int y = s; y < e; y++) {
                    const float4 v = *p; p += W4;
                    m.x = fmaxf(m.x, v.x);
                    m.y = fmaxf(m.y, v.y);
                    m.z = fmaxf(m.z, v.z);
                    m.w = fmaxf(m.w, v.w);
                }
                *(float4*)&rowc[i * ROWP_STRIDE + q * 4] = m;
            }
        }
    }
    __syncthreads();

    // ---- Phase 2: col-bin maxes from shared ----
    float* __restrict__ outg = out + ((size_t)r * Cc + cg * CPB) * (OUTN * OUTN);
    for (int o = tid; o < CPB * OUTN * OUTN; o += 256) {
        const int cc = o / (OUTN * OUTN);
        const int ij = o - cc * (OUTN * OUTN);
        const int i = ij / OUTN;
        const int j = ij - i * OUTN;
        const int s = sb[14 + j], e = sb[21 + j];
        const float* rp = rowp + cc * (OUTN * ROWP_STRIDE) + i * ROWP_STRIDE;
        float m = -FLT_MAX;
        for (int x = s; x < e; x++)
            m = fmaxf(m, rp[x]);
        outg[o] = m;   // contiguous per stride-pass -> coalesced
    }
}

#define SMEM_BYTES (CPB * OUTN * ROWP_STRIDE * 4 + 32 * 4)

extern "C" void kernel_launch(void* const* d_in, const int* in_sizes, int n_in,
                              void* d_out, int out_size) {
    const float* images  = (const float*)d_in[0];
    const float* rois    = (const float*)d_in[1];
    const int*   roi_idx = (const int*)d_in[2];
    float* out = (float*)d_out;

    // Host-side attribute set (idempotent, not a stream op -> capture-safe)
    cudaFuncSetAttribute(roipool_kernel,
                         cudaFuncAttributeMaxDynamicSharedMemorySize, SMEM_BYTES);

    dim3 grid(Cc / CPB, Rc);   // (8, 256) = 2048 blocks
    dim3 block(8, CPB);        // 256 threads
    roipool_kernel<<<grid, block, SMEM_BYTES>>>(images, rois, roi_idx, out);
}

// round 8
// speedup vs baseline: 1.2289x; 1.2289x over previous
#include <cuda_runtime.h>
#include <float.h>

// ROI adaptive max pool 7x7 — R5 structure + warp-uniform trip-count
// specialization (switch on bin length -> straight-line unrolled bodies).
// images: [8,256,56,56] f32; rois: [256,4] f32; roi_idx: [256] i32
// out: [256,256,7,7] f32

#define Hc 56
#define Wc 56
#define Cc 256
#define Rc 256
#define OUTN 7
#define CPB 16
#define W4 (Wc / 4)   // 14

__device__ __forceinline__ float4 fm4(float4 a, float4 b) {
    return make_float4(fmaxf(a.x, b.x), fmaxf(a.y, b.y),
                       fmaxf(a.z, b.z), fmaxf(a.w, b.w));
}

__global__ __launch_bounds__(256, 6) void roipool_kernel(
    const float* __restrict__ images,
    const float* __restrict__ rois,
    const int* __restrict__ roi_idx,
    float* __restrict__ out)
{
    __shared__ float rowp[CPB][OUTN][60];
    __shared__ int sb[28];   // ys[7] ye[7] xs[7] xe[7]

    const int r  = blockIdx.y;
    const int cg = blockIdx.x;
    const int tx = threadIdx.x;            // 0..15 quad
    const int ty = threadIdx.y;            // 0..15 channel
    const int tid = ty * 16 + tx;

    const float4 rv = ((const float4*)rois)[r];
    const int x1 = (int)floorf(rv.x * (float)Wc);
    const int y1 = (int)floorf(rv.y * (float)Hc);
    const int x2 = (int)ceilf (rv.z * (float)Wc);
    const int y2 = (int)ceilf (rv.w * (float)Hc);

    if (tid < 28) {
        const int g = tid / OUTN;          // 0:ys 1:ye 2:xs 3:xe
        const int i = tid - g * OUTN;
        const int Hr = y2 - y1, Wr = x2 - x1;
        int v;
        if (g == 0)      v = y1 + (i * Hr) / OUTN;
        else if (g == 1) v = y1 + ((i + 1) * Hr + OUTN - 1) / OUTN;
        else if (g == 2) v = x1 + (i * Wr) / OUTN;
        else             v = x1 + ((i + 1) * Wr + OUTN - 1) / OUTN;
        sb[tid] = v;
    }
    __syncthreads();

    const int n_img = roi_idx[r];
    const float* __restrict__ img =
        images + (size_t)(n_img * Cc + cg * CPB + ty) * (Hc * Wc);

    // ---- Phase 1: row-bin maxes, trip-count-specialized ----
    const int qlo = x1 >> 2;
    const int qhi = (x2 + 3) >> 2;
    if (tx >= qlo && tx < qhi) {
        const float4* __restrict__ base = (const float4*)img + tx;
        #pragma unroll
        for (int i = 0; i < OUTN; i++) {
            const int s = sb[i];
            const int n = sb[7 + i] - s;   // warp-uniform, typically 2..4
            const float4* __restrict__ p = base + s * W4;
            float4 m;
            switch (n) {
            case 1: {
                m = p[0];
            } break;
            case 2: {
                const float4 a = p[0], b = p[W4];
                m = fm4(a, b);
            } break;
            case 3: {
                const float4 a = p[0], b = p[W4], c = p[2 * W4];
                m = fm4(fm4(a, b), c);
            } break;
            case 4: {
                const float4 a = p[0], b = p[W4];
                const float4 c = p[2 * W4], d = p[3 * W4];
                m = fm4(fm4(a, b), fm4(c, d));
            } break;
            default: {
                m = make_float4(-FLT_MAX, -FLT_MAX, -FLT_MAX, -FLT_MAX);
                if (n > 0) {
                    m = p[0];
                    #pragma unroll 2
                    for (int y = 1; y < n; y++)
                        m = fm4(m, p[y * W4]);
                }
            } break;
            }
            *(float4*)&rowp[ty][i][tx * 4] = m;
        }
    }
    __syncthreads();

    // ---- Phase 2: col-bin maxes from shared, trip-count-specialized ----
    float* __restrict__ outg = out + ((size_t)r * Cc + cg * CPB) * (OUTN * OUTN);
    #pragma unroll
    for (int o = tid; o < CPB * OUTN * OUTN; o += 256) {
        const int cc = o / (OUTN * OUTN);
        const int ij = o - cc * (OUTN * OUTN);
        const int i = ij / OUTN;
        const int j = ij - i * OUTN;
        const int s = sb[14 + j];
        const int n = sb[21 + j] - s;      // 1..9 typical 2..4
        const float* __restrict__ rp = &rowp[cc][i][s];
        float m;
        switch (n) {
        case 1: m = rp[0]; break;
        case 2: m = fmaxf(rp[0], rp[1]); break;
        case 3: m = fmaxf(fmaxf(rp[0], rp[1]), rp[2]); break;
        case 4: m = fmaxf(fmaxf(rp[0], rp[1]), fmaxf(rp[2], rp[3])); break;
        default: {
            m = -FLT_MAX;
            if (n > 0) {
                m = rp[0];
                #pragma unroll 2
                for (int x = 1; x < n; x++)
                    m = fmaxf(m, rp[x]);
            }
        } break;
        }
        outg[o] = m;   // contiguous per stride-pass -> coalesced
    }
}

extern "C" void kernel_launch(void* const* d_in, const int* in_sizes, int n_in,
                              void* d_out, int out_size) {
    const float* images  = (const float*)d_in[0];
    const float* rois    = (const float*)d_in[1];
    const int*   roi_idx = (const int*)d_in[2];
    float* out = (float*)d_out;

    dim3 grid(Cc / CPB, Rc);   // (16, 256) = 4096 blocks
    dim3 block(16, 16);        // 256 threads
    roipool_kernel<<<grid, block>>>(images, rois, roi_idx, out);
}